// round 1
// baseline (speedup 1.0000x reference)
#include <cuda_runtime.h>
#include <math.h>

#define VOCAB 32000
#define EMBED 512
#define KQD   512
#define VDIM  512
#define NB    2
#define SEQ   2048
#define NTOK  (NB * SEQ)

// ---------------- scratch (__device__ globals; no allocation allowed) -------
__device__ float g_h[NTOK * EMBED];          // 8 MB
__device__ float g_Q[NTOK * KQD];            // 8 MB
__device__ float g_K[NTOK * KQD];            // 8 MB
__device__ float g_V[NTOK * VDIM];           // 8 MB
__device__ float g_S[(size_t)NB * SEQ * SEQ];// 33.5 MB (scores -> attn)
__device__ float g_C[NTOK * VDIM];           // 8 MB (context)

// ---------------- stage 1: h = emb[x] + sinusoidal PE -----------------------
__global__ void embed_pe_kernel(const int* __restrict__ x,
                                const float* __restrict__ emb) {
    int tok = blockIdx.x;             // 0..NTOK-1
    int s = tok & (SEQ - 1);          // position within sequence
    const float* e = emb + (size_t)x[tok] * EMBED;
    float* o = g_h + (size_t)tok * EMBED;
    for (int i = threadIdx.x; i < EMBED; i += blockDim.x) {
        int j = i >> 1;
        float freq = expf((float)(2 * j) * (-9.210340371976184f / (float)EMBED));
        float ang = (float)s * freq;
        float pe = (i & 1) ? cosf(ang) : sinf(ang);
        o[i] = e[i] + pe;
    }
}

// ---------------- generic 128x128x16 fp32 tiled GEMM ------------------------
// C[M,N] = scale * (A[M,K] x B)  (+ bias[n])
//   BNT=true : B is [N,K] row-major (NT gemm, dot of rows)
//   BNT=false: B is [K,N] row-major (NN gemm)
//   CAUSAL: skip blocks fully above the diagonal (n0 > m0+127)
// Batch via blockIdx.z with strides sA/sB/sC.
template <bool BNT, bool CAUSAL, bool BIAS>
__global__ __launch_bounds__(256)
void gemm128(const float* __restrict__ Ag, const float* __restrict__ Bg,
             float* __restrict__ Cg, const float* __restrict__ bias,
             int M, int N, int K, float scale,
             size_t sA, size_t sB, size_t sC) {
    const int n0 = blockIdx.x * 128;
    const int m0 = blockIdx.y * 128;
    if (CAUSAL && n0 > m0 + 127) return;  // fully-masked tile, never read

    const float* A = Ag + (size_t)blockIdx.z * sA;
    const float* B = Bg + (size_t)blockIdx.z * sB;
    float* C       = Cg + (size_t)blockIdx.z * sC;

    __shared__ float As[16][132];
    __shared__ float Bs[16][132];

    const int tid = threadIdx.x;
    const int tx = tid & 15;   // -> n
    const int ty = tid >> 4;   // -> m

    float acc[8][8] = {};

    for (int k0 = 0; k0 < K; k0 += 16) {
        // load A tile [128 x 16], transpose into As[k][m]
#pragma unroll
        for (int l = 0; l < 2; l++) {
            int idx = tid + l * 256;       // 0..511 float4s
            int row = idx >> 2;            // 0..127
            int c4  = idx & 3;             // 0..3
            float4 v = *(const float4*)&A[(size_t)(m0 + row) * K + k0 + c4 * 4];
            As[c4 * 4 + 0][row] = v.x;
            As[c4 * 4 + 1][row] = v.y;
            As[c4 * 4 + 2][row] = v.z;
            As[c4 * 4 + 3][row] = v.w;
        }
        if (BNT) {
#pragma unroll
            for (int l = 0; l < 2; l++) {
                int idx = tid + l * 256;
                int row = idx >> 2;
                int c4  = idx & 3;
                float4 v = *(const float4*)&B[(size_t)(n0 + row) * K + k0 + c4 * 4];
                Bs[c4 * 4 + 0][row] = v.x;
                Bs[c4 * 4 + 1][row] = v.y;
                Bs[c4 * 4 + 2][row] = v.z;
                Bs[c4 * 4 + 3][row] = v.w;
            }
        } else {
#pragma unroll
            for (int l = 0; l < 2; l++) {
                int idx = tid + l * 256;
                int kr = idx >> 5;         // 0..15
                int c4 = idx & 31;         // 0..31
                float4 v = *(const float4*)&B[(size_t)(k0 + kr) * N + n0 + c4 * 4];
                *(float4*)&Bs[kr][c4 * 4] = v;
            }
        }
        __syncthreads();

#pragma unroll
        for (int kk = 0; kk < 16; kk++) {
            float a[8], b[8];
            *(float4*)&a[0] = *(const float4*)&As[kk][ty * 8];
            *(float4*)&a[4] = *(const float4*)&As[kk][ty * 8 + 4];
            *(float4*)&b[0] = *(const float4*)&Bs[kk][tx * 8];
            *(float4*)&b[4] = *(const float4*)&Bs[kk][tx * 8 + 4];
#pragma unroll
            for (int i = 0; i < 8; i++)
#pragma unroll
                for (int j = 0; j < 8; j++)
                    acc[i][j] += a[i] * b[j];
        }
        __syncthreads();
    }

#pragma unroll
    for (int i = 0; i < 8; i++) {
        size_t m = (size_t)(m0 + ty * 8 + i);
        float* crow = C + m * (size_t)N + n0 + tx * 8;
#pragma unroll
        for (int jq = 0; jq < 2; jq++) {
            int nb = n0 + tx * 8 + jq * 4;
            float4 v;
            v.x = acc[i][jq * 4 + 0] * scale;
            v.y = acc[i][jq * 4 + 1] * scale;
            v.z = acc[i][jq * 4 + 2] * scale;
            v.w = acc[i][jq * 4 + 3] * scale;
            if (BIAS) {
                v.x += bias[nb + 0];
                v.y += bias[nb + 1];
                v.z += bias[nb + 2];
                v.w += bias[nb + 3];
            }
            *(float4*)&crow[jq * 4] = v;
        }
    }
}

// ---------------- stage 4: causal row softmax (in place on g_S) -------------
__global__ void softmax_causal_kernel() {
    int row = blockIdx.x;             // 0..NTOK-1
    int b = row / SEQ;
    int q = row & (SEQ - 1);
    float* r = g_S + (size_t)b * SEQ * SEQ + (size_t)q * SEQ;
    const int len = q + 1;

    __shared__ float redm[8];
    __shared__ float reds[8];
    __shared__ float bc[2];

    // pass 1: max
    float m = -INFINITY;
    for (int i = threadIdx.x; i < len; i += 256) m = fmaxf(m, r[i]);
#pragma unroll
    for (int o = 16; o; o >>= 1) m = fmaxf(m, __shfl_xor_sync(0xffffffffu, m, o));
    if ((threadIdx.x & 31) == 0) redm[threadIdx.x >> 5] = m;
    __syncthreads();
    if (threadIdx.x == 0) {
        float v = redm[0];
#pragma unroll
        for (int w = 1; w < 8; w++) v = fmaxf(v, redm[w]);
        bc[0] = v;
    }
    __syncthreads();
    const float rmax = bc[0];

    // pass 2: exp + sum (store unnormalized exp)
    float s = 0.f;
    for (int i = threadIdx.x; i < len; i += 256) {
        float e = __expf(r[i] - rmax);
        r[i] = e;
        s += e;
    }
#pragma unroll
    for (int o = 16; o; o >>= 1) s += __shfl_xor_sync(0xffffffffu, s, o);
    if ((threadIdx.x & 31) == 0) reds[threadIdx.x >> 5] = s;
    __syncthreads();
    if (threadIdx.x == 0) {
        float v = reds[0];
#pragma unroll
        for (int w = 1; w < 8; w++) v += reds[w];
        bc[1] = 1.0f / v;
    }
    __syncthreads();
    const float inv = bc[1];

    // pass 3: normalize + zero-fill masked tail (so ctx GEMM is a plain NN gemm)
    for (int i = threadIdx.x; i < len; i += 256) r[i] *= inv;
    for (int i = len + threadIdx.x; i < SEQ; i += 256) r[i] = 0.f;
}

// ---------------- launch ----------------------------------------------------
extern "C" void kernel_launch(void* const* d_in, const int* in_sizes, int n_in,
                              void* d_out, int out_size) {
    const int*   x   = (const int*)d_in[0];
    const float* emb = (const float*)d_in[1];
    const float* Wq  = (const float*)d_in[2];
    const float* Wk  = (const float*)d_in[3];
    const float* Wv  = (const float*)d_in[4];
    const float* Wh  = (const float*)d_in[5];
    const float* bh  = (const float*)d_in[6];
    float* out = (float*)d_out;

    float *h, *Q, *K, *V, *S, *C;
    cudaGetSymbolAddress((void**)&h, g_h);
    cudaGetSymbolAddress((void**)&Q, g_Q);
    cudaGetSymbolAddress((void**)&K, g_K);
    cudaGetSymbolAddress((void**)&V, g_V);
    cudaGetSymbolAddress((void**)&S, g_S);
    cudaGetSymbolAddress((void**)&C, g_C);

    const dim3 blk(256);
    const float sscale = 22.627416997969522f;  // sqrt(512): ref divides by d^-0.5

    // 1) embedding + positional encoding
    embed_pe_kernel<<<NTOK, 128>>>(x, emb);

    // 2) Q/K/V projections (NT: W is [out,in] row-major)
    gemm128<true, false, false><<<dim3(KQD / 128, NTOK / 128, 1), blk>>>(
        h, Wq, Q, nullptr, NTOK, KQD, EMBED, 1.f, 0, 0, 0);
    gemm128<true, false, false><<<dim3(KQD / 128, NTOK / 128, 1), blk>>>(
        h, Wk, K, nullptr, NTOK, KQD, EMBED, 1.f, 0, 0, 0);
    gemm128<true, false, false><<<dim3(VDIM / 128, NTOK / 128, 1), blk>>>(
        h, Wv, V, nullptr, NTOK, VDIM, EMBED, 1.f, 0, 0, 0);

    // 3) scores = sqrt(512) * Q K^T, causal tiles skipped
    gemm128<true, true, false><<<dim3(SEQ / 128, SEQ / 128, NB), blk>>>(
        Q, K, S, nullptr, SEQ, SEQ, KQD, sscale,
        (size_t)SEQ * KQD, (size_t)SEQ * KQD, (size_t)SEQ * SEQ);

    // 4) causal softmax in place
    softmax_causal_kernel<<<NTOK, 256>>>();

    // 5) ctx = attn @ V  (NN gemm; attn is zero above the diagonal)
    gemm128<false, false, false><<<dim3(VDIM / 128, SEQ / 128, NB), blk>>>(
        S, V, C, nullptr, SEQ, VDIM, SEQ, 1.f,
        (size_t)SEQ * SEQ, (size_t)SEQ * VDIM, (size_t)SEQ * VDIM);

    // 6) logits = ctx @ Wh^T + bh   (the 134 GF monster)
    gemm128<true, false, true><<<dim3(VOCAB / 128, NTOK / 128, 1), blk>>>(
        C, Wh, out, bh, NTOK, VOCAB, VDIM, 1.f, 0, 0, 0);
}

// round 2
// speedup vs baseline: 2.0551x; 2.0551x over previous
#include <cuda_runtime.h>
#include <math.h>
#include <stdint.h>

#define VOCAB 32000
#define EMBED 512
#define KQD   512
#define VDIM  512
#define NB    2
#define SEQ   2048
#define NTOK  (NB * SEQ)

// ---------------- scratch (__device__ globals; no allocation allowed) -------
__device__ float g_h[NTOK * EMBED];          // 8 MB
__device__ float g_Q[NTOK * KQD];            // 8 MB
__device__ float g_K[NTOK * KQD];            // 8 MB
__device__ float g_V[NTOK * VDIM];           // 8 MB
__device__ float g_S[(size_t)NB * SEQ * SEQ];// 33.5 MB (scores -> attn)
__device__ float g_C[NTOK * VDIM];           // 8 MB (context)

// ---------------- stage 1: h = emb[x] + sinusoidal PE -----------------------
__global__ void embed_pe_kernel(const int* __restrict__ x,
                                const float* __restrict__ emb) {
    int tok = blockIdx.x;             // 0..NTOK-1
    int s = tok & (SEQ - 1);          // position within sequence
    const float* e = emb + (size_t)x[tok] * EMBED;
    float* o = g_h + (size_t)tok * EMBED;
    for (int i = threadIdx.x; i < EMBED; i += blockDim.x) {
        int j = i >> 1;
        float freq = expf((float)(2 * j) * (-9.210340371976184f / (float)EMBED));
        float ang = (float)s * freq;
        float pe = (i & 1) ? cosf(ang) : sinf(ang);
        o[i] = e[i] + pe;
    }
}

// ---------------- generic 128x128x16 fp32 tiled GEMM (attention path) -------
template <bool BNT, bool CAUSAL, bool BIAS>
__global__ __launch_bounds__(256)
void gemm128(const float* __restrict__ Ag, const float* __restrict__ Bg,
             float* __restrict__ Cg, const float* __restrict__ bias,
             int M, int N, int K, float scale,
             size_t sA, size_t sB, size_t sC) {
    const int n0 = blockIdx.x * 128;
    const int m0 = blockIdx.y * 128;
    if (CAUSAL && n0 > m0 + 127) return;  // fully-masked tile, never read

    const float* A = Ag + (size_t)blockIdx.z * sA;
    const float* B = Bg + (size_t)blockIdx.z * sB;
    float* C       = Cg + (size_t)blockIdx.z * sC;

    __shared__ float As[16][132];
    __shared__ float Bs[16][132];

    const int tid = threadIdx.x;
    const int tx = tid & 15;   // -> n
    const int ty = tid >> 4;   // -> m

    float acc[8][8] = {};

    for (int k0 = 0; k0 < K; k0 += 16) {
#pragma unroll
        for (int l = 0; l < 2; l++) {
            int idx = tid + l * 256;
            int row = idx >> 2;
            int c4  = idx & 3;
            float4 v = *(const float4*)&A[(size_t)(m0 + row) * K + k0 + c4 * 4];
            As[c4 * 4 + 0][row] = v.x;
            As[c4 * 4 + 1][row] = v.y;
            As[c4 * 4 + 2][row] = v.z;
            As[c4 * 4 + 3][row] = v.w;
        }
        if (BNT) {
#pragma unroll
            for (int l = 0; l < 2; l++) {
                int idx = tid + l * 256;
                int row = idx >> 2;
                int c4  = idx & 3;
                float4 v = *(const float4*)&B[(size_t)(n0 + row) * K + k0 + c4 * 4];
                Bs[c4 * 4 + 0][row] = v.x;
                Bs[c4 * 4 + 1][row] = v.y;
                Bs[c4 * 4 + 2][row] = v.z;
                Bs[c4 * 4 + 3][row] = v.w;
            }
        } else {
#pragma unroll
            for (int l = 0; l < 2; l++) {
                int idx = tid + l * 256;
                int kr = idx >> 5;
                int c4 = idx & 31;
                float4 v = *(const float4*)&B[(size_t)(k0 + kr) * N + n0 + c4 * 4];
                *(float4*)&Bs[kr][c4 * 4] = v;
            }
        }
        __syncthreads();

#pragma unroll
        for (int kk = 0; kk < 16; kk++) {
            float a[8], b[8];
            *(float4*)&a[0] = *(const float4*)&As[kk][ty * 8];
            *(float4*)&a[4] = *(const float4*)&As[kk][ty * 8 + 4];
            *(float4*)&b[0] = *(const float4*)&Bs[kk][tx * 8];
            *(float4*)&b[4] = *(const float4*)&Bs[kk][tx * 8 + 4];
#pragma unroll
            for (int i = 0; i < 8; i++)
#pragma unroll
                for (int j = 0; j < 8; j++)
                    acc[i][j] += a[i] * b[j];
        }
        __syncthreads();
    }

#pragma unroll
    for (int i = 0; i < 8; i++) {
        size_t m = (size_t)(m0 + ty * 8 + i);
        float* crow = C + m * (size_t)N + n0 + tx * 8;
#pragma unroll
        for (int jq = 0; jq < 2; jq++) {
            int nb = n0 + tx * 8 + jq * 4;
            float4 v;
            v.x = acc[i][jq * 4 + 0] * scale;
            v.y = acc[i][jq * 4 + 1] * scale;
            v.z = acc[i][jq * 4 + 2] * scale;
            v.w = acc[i][jq * 4 + 3] * scale;
            if (BIAS) {
                v.x += bias[nb + 0];
                v.y += bias[nb + 1];
                v.z += bias[nb + 2];
                v.w += bias[nb + 3];
            }
            *(float4*)&crow[jq * 4] = v;
        }
    }
}

// ---------------- tf32 tensor-core GEMM for logits --------------------------
// C[M,N] = A[M,K] @ B[N,K]^T + bias ; M=4096, N=32000, K=512.
// CTA 128x128, BK=16, double-buffered smem, 8 warps as 2(M) x 4(N).
// Row pad 20 floats: frag addr = 20*qr + qc -> (4*qr + qc) mod 32 distinct.

__device__ __forceinline__ uint32_t f2tf32(float f) {
    uint32_t r;
    asm("cvt.rna.tf32.f32 %0, %1;" : "=r"(r) : "f"(f));
    return r;
}

__device__ __forceinline__ void mma_tf32(float* acc, uint32_t a0, uint32_t a1,
                                         uint32_t a2, uint32_t a3,
                                         uint32_t b0, uint32_t b1) {
    asm("mma.sync.aligned.m16n8k8.row.col.f32.tf32.tf32.f32 "
        "{%0,%1,%2,%3}, {%4,%5,%6,%7}, {%8,%9}, {%0,%1,%2,%3};"
        : "+f"(acc[0]), "+f"(acc[1]), "+f"(acc[2]), "+f"(acc[3])
        : "r"(a0), "r"(a1), "r"(a2), "r"(a3), "r"(b0), "r"(b1));
}

#define LPAD 20

__global__ __launch_bounds__(256)
void tf32_logits_gemm(const float* __restrict__ A,   // ctx [4096][512]
                      const float* __restrict__ B,   // Wh  [32000][512]
                      const float* __restrict__ bias,
                      float* __restrict__ C) {
    const int M = NTOK, N = VOCAB, K = VDIM;
    const int m0 = blockIdx.x * 128;   // x = M tiles: consecutive CTAs share Wh tile in L2
    const int n0 = blockIdx.y * 128;

    __shared__ float As[2][128][LPAD];
    __shared__ float Bs[2][128][LPAD];

    const int tid = threadIdx.x;
    const int lane = tid & 31;
    const int wid = tid >> 5;
    const int warpM = wid >> 2;        // 0..1
    const int warpN = wid & 3;         // 0..3
    const int qr = lane >> 2;          // 0..7
    const int qc = lane & 3;           // 0..3

    // fill indices: 512 float4 per tile / 256 thr = 2 each
    const int frow0 = tid >> 2;            // for l=0: rows 0..63
    const int frow1 = (tid + 256) >> 2;    // rows 64..127
    const int fc4 = tid & 3;

    float acc[4][4][4] = {};  // [mt][nt][reg]

    float4 av[2], bv[2];
    // prologue: load k-tile 0
    av[0] = *(const float4*)&A[(m0 + frow0) * K + fc4 * 4];
    av[1] = *(const float4*)&A[(m0 + frow1) * K + fc4 * 4];
    bv[0] = *(const float4*)&B[(n0 + frow0) * K + fc4 * 4];
    bv[1] = *(const float4*)&B[(n0 + frow1) * K + fc4 * 4];
#pragma unroll
    for (int l = 0; l < 2; l++) {
        int row = l ? frow1 : frow0;
        float4 va = l ? av[1] : av[0];
        float4 vb = l ? bv[1] : bv[0];
        float4 ca, cb;
        ca.x = __uint_as_float(f2tf32(va.x)); ca.y = __uint_as_float(f2tf32(va.y));
        ca.z = __uint_as_float(f2tf32(va.z)); ca.w = __uint_as_float(f2tf32(va.w));
        cb.x = __uint_as_float(f2tf32(vb.x)); cb.y = __uint_as_float(f2tf32(vb.y));
        cb.z = __uint_as_float(f2tf32(vb.z)); cb.w = __uint_as_float(f2tf32(vb.w));
        *(float4*)&As[0][row][fc4 * 4] = ca;
        *(float4*)&Bs[0][row][fc4 * 4] = cb;
    }
    __syncthreads();

    const int NIT = K / 16;  // 32
    for (int it = 0; it < NIT; it++) {
        const int cur = it & 1;
        // prefetch next k-tile into registers (overlaps with compute)
        if (it + 1 < NIT) {
            int k0 = (it + 1) * 16;
            av[0] = *(const float4*)&A[(m0 + frow0) * K + k0 + fc4 * 4];
            av[1] = *(const float4*)&A[(m0 + frow1) * K + k0 + fc4 * 4];
            bv[0] = *(const float4*)&B[(n0 + frow0) * K + k0 + fc4 * 4];
            bv[1] = *(const float4*)&B[(n0 + frow1) * K + k0 + fc4 * 4];
        }

        // compute on cur buffer: 2 k-steps of 8
#pragma unroll
        for (int ks = 0; ks < 2; ks++) {
            uint32_t af[4][4], bf[4][2];
#pragma unroll
            for (int mt = 0; mt < 4; mt++) {
                int r = warpM * 64 + mt * 16 + qr;
                af[mt][0] = __float_as_uint(As[cur][r][ks * 8 + qc]);
                af[mt][1] = __float_as_uint(As[cur][r + 8][ks * 8 + qc]);
                af[mt][2] = __float_as_uint(As[cur][r][ks * 8 + qc + 4]);
                af[mt][3] = __float_as_uint(As[cur][r + 8][ks * 8 + qc + 4]);
            }
#pragma unroll
            for (int nt = 0; nt < 4; nt++) {
                int r = warpN * 32 + nt * 8 + qr;
                bf[nt][0] = __float_as_uint(Bs[cur][r][ks * 8 + qc]);
                bf[nt][1] = __float_as_uint(Bs[cur][r][ks * 8 + qc + 4]);
            }
#pragma unroll
            for (int mt = 0; mt < 4; mt++)
#pragma unroll
                for (int nt = 0; nt < 4; nt++)
                    mma_tf32(acc[mt][nt], af[mt][0], af[mt][1], af[mt][2],
                             af[mt][3], bf[nt][0], bf[nt][1]);
        }
        __syncthreads();   // everyone done reading buffers before refill

        if (it + 1 < NIT) {
            const int nxt = cur ^ 1;
#pragma unroll
            for (int l = 0; l < 2; l++) {
                int row = l ? frow1 : frow0;
                float4 va = l ? av[1] : av[0];
                float4 vb = l ? bv[1] : bv[0];
                float4 ca, cb;
                ca.x = __uint_as_float(f2tf32(va.x)); ca.y = __uint_as_float(f2tf32(va.y));
                ca.z = __uint_as_float(f2tf32(va.z)); ca.w = __uint_as_float(f2tf32(va.w));
                cb.x = __uint_as_float(f2tf32(vb.x)); cb.y = __uint_as_float(f2tf32(vb.y));
                cb.z = __uint_as_float(f2tf32(vb.z)); cb.w = __uint_as_float(f2tf32(vb.w));
                *(float4*)&As[nxt][row][fc4 * 4] = ca;
                *(float4*)&Bs[nxt][row][fc4 * 4] = cb;
            }
            __syncthreads();
        }
    }

    // epilogue: C += bias, float2 stores
#pragma unroll
    for (int mt = 0; mt < 4; mt++) {
        int r = m0 + warpM * 64 + mt * 16 + qr;
#pragma unroll
        for (int nt = 0; nt < 4; nt++) {
            int c = n0 + warpN * 32 + nt * 8 + qc * 2;
            float2 bb = *(const float2*)&bias[c];
            float2 v0, v1;
            v0.x = acc[mt][nt][0] + bb.x;
            v0.y = acc[mt][nt][1] + bb.y;
            v1.x = acc[mt][nt][2] + bb.x;
            v1.y = acc[mt][nt][3] + bb.y;
            *(float2*)&C[(size_t)r * N + c] = v0;
            *(float2*)&C[(size_t)(r + 8) * N + c] = v1;
        }
    }
}

// ---------------- stage 4: causal row softmax (in place on g_S) -------------
__global__ void softmax_causal_kernel() {
    int row = blockIdx.x;
    int b = row / SEQ;
    int q = row & (SEQ - 1);
    float* r = g_S + (size_t)b * SEQ * SEQ + (size_t)q * SEQ;
    const int len = q + 1;

    __shared__ float redm[8];
    __shared__ float reds[8];
    __shared__ float bc[2];

    float m = -INFINITY;
    for (int i = threadIdx.x; i < len; i += 256) m = fmaxf(m, r[i]);
#pragma unroll
    for (int o = 16; o; o >>= 1) m = fmaxf(m, __shfl_xor_sync(0xffffffffu, m, o));
    if ((threadIdx.x & 31) == 0) redm[threadIdx.x >> 5] = m;
    __syncthreads();
    if (threadIdx.x == 0) {
        float v = redm[0];
#pragma unroll
        for (int w = 1; w < 8; w++) v = fmaxf(v, redm[w]);
        bc[0] = v;
    }
    __syncthreads();
    const float rmax = bc[0];

    float s = 0.f;
    for (int i = threadIdx.x; i < len; i += 256) {
        float e = __expf(r[i] - rmax);
        r[i] = e;
        s += e;
    }
#pragma unroll
    for (int o = 16; o; o >>= 1) s += __shfl_xor_sync(0xffffffffu, s, o);
    if ((threadIdx.x & 31) == 0) reds[threadIdx.x >> 5] = s;
    __syncthreads();
    if (threadIdx.x == 0) {
        float v = reds[0];
#pragma unroll
        for (int w = 1; w < 8; w++) v += reds[w];
        bc[1] = 1.0f / v;
    }
    __syncthreads();
    const float inv = bc[1];

    for (int i = threadIdx.x; i < len; i += 256) r[i] *= inv;
    for (int i = len + threadIdx.x; i < SEQ; i += 256) r[i] = 0.f;
}

// ---------------- launch ----------------------------------------------------
extern "C" void kernel_launch(void* const* d_in, const int* in_sizes, int n_in,
                              void* d_out, int out_size) {
    const int*   x   = (const int*)d_in[0];
    const float* emb = (const float*)d_in[1];
    const float* Wq  = (const float*)d_in[2];
    const float* Wk  = (const float*)d_in[3];
    const float* Wv  = (const float*)d_in[4];
    const float* Wh  = (const float*)d_in[5];
    const float* bh  = (const float*)d_in[6];
    float* out = (float*)d_out;

    float *h, *Q, *K, *V, *S, *C;
    cudaGetSymbolAddress((void**)&h, g_h);
    cudaGetSymbolAddress((void**)&Q, g_Q);
    cudaGetSymbolAddress((void**)&K, g_K);
    cudaGetSymbolAddress((void**)&V, g_V);
    cudaGetSymbolAddress((void**)&S, g_S);
    cudaGetSymbolAddress((void**)&C, g_C);

    const dim3 blk(256);
    const float sscale = 22.627416997969522f;  // sqrt(512): ref divides by d^-0.5

    // 1) embedding + positional encoding
    embed_pe_kernel<<<NTOK, 128>>>(x, emb);

    // 2) Q/K/V projections (fp32 — attention path is precision-critical)
    gemm128<true, false, false><<<dim3(KQD / 128, NTOK / 128, 1), blk>>>(
        h, Wq, Q, nullptr, NTOK, KQD, EMBED, 1.f, 0, 0, 0);
    gemm128<true, false, false><<<dim3(KQD / 128, NTOK / 128, 1), blk>>>(
        h, Wk, K, nullptr, NTOK, KQD, EMBED, 1.f, 0, 0, 0);
    gemm128<true, false, false><<<dim3(VDIM / 128, NTOK / 128, 1), blk>>>(
        h, Wv, V, nullptr, NTOK, VDIM, EMBED, 1.f, 0, 0, 0);

    // 3) scores = sqrt(512) * Q K^T (fp32, causal tiles skipped)
    gemm128<true, true, false><<<dim3(SEQ / 128, SEQ / 128, NB), blk>>>(
        Q, K, S, nullptr, SEQ, SEQ, KQD, sscale,
        (size_t)SEQ * KQD, (size_t)SEQ * KQD, (size_t)SEQ * SEQ);

    // 4) causal softmax in place
    softmax_causal_kernel<<<NTOK, 256>>>();

    // 5) ctx = attn @ V (fp32 NN gemm; attn zero above diagonal)
    gemm128<false, false, false><<<dim3(VDIM / 128, SEQ / 128, NB), blk>>>(
        S, V, C, nullptr, SEQ, VDIM, SEQ, 1.f,
        (size_t)SEQ * SEQ, (size_t)SEQ * VDIM, (size_t)SEQ * VDIM);

    // 6) logits = ctx @ Wh^T + bh — tf32 tensor cores (134 GF of the 157 GF total)
    tf32_logits_gemm<<<dim3(NTOK / 128, VOCAB / 128), blk>>>(C, Wh, bh, out);
}

// round 3
// speedup vs baseline: 2.2259x; 1.0831x over previous
#include <cuda_runtime.h>
#include <math.h>
#include <stdint.h>

#define VOCAB 32000
#define EMBED 512
#define KQD   512
#define VDIM  512
#define NB    2
#define SEQ   2048
#define NTOK  (NB * SEQ)
#define LPAD  20

// ---------------- scratch (__device__ globals; no allocation allowed) -------
__device__ float g_h[NTOK * EMBED];
__device__ float g_Q[NTOK * KQD];
__device__ float g_K[NTOK * KQD];
__device__ float g_V[NTOK * VDIM];
__device__ float g_S[(size_t)NB * SEQ * SEQ];
__device__ float g_C[NTOK * VDIM];

struct GemmPtrs {
    const float* A[3];
    const float* B[3];
    float*       C[3];
};

// ---------------- stage 1: h = emb[x] + sinusoidal PE -----------------------
__global__ void embed_pe_kernel(const int* __restrict__ x,
                                const float* __restrict__ emb) {
    int tok = blockIdx.x;
    int s = tok & (SEQ - 1);
    const float* e = emb + (size_t)x[tok] * EMBED;
    float* o = g_h + (size_t)tok * EMBED;
    for (int i = threadIdx.x; i < EMBED; i += blockDim.x) {
        int j = i >> 1;
        float freq = expf((float)(2 * j) * (-9.210340371976184f / (float)EMBED));
        float ang = (float)s * freq;
        float pe = (i & 1) ? cosf(ang) : sinf(ang);
        o[i] = e[i] + pe;
    }
}

// ---------------- tf32 helpers ----------------------------------------------
__device__ __forceinline__ uint32_t f2tf32(float f) {
    uint32_t r;
    asm("cvt.rna.tf32.f32 %0, %1;" : "=r"(r) : "f"(f));
    return r;
}

__device__ __forceinline__ void mma_tf32(float* acc, const uint32_t* a,
                                         const uint32_t* b) {
    asm("mma.sync.aligned.m16n8k8.row.col.f32.tf32.tf32.f32 "
        "{%0,%1,%2,%3}, {%4,%5,%6,%7}, {%8,%9}, {%0,%1,%2,%3};"
        : "+f"(acc[0]), "+f"(acc[1]), "+f"(acc[2]), "+f"(acc[3])
        : "r"(a[0]), "r"(a[1]), "r"(a[2]), "r"(a[3]), "r"(b[0]), "r"(b[1]));
}

// ---------------- unified tensor-core GEMM -----------------------------------
// C[M,N] = scale * (A[M,K] @ op(B)) + bias
//   BNT=true : B is [N,K] row-major; BNT=false: B is [K,N] row-major.
//   NPASS=3: 3xTF32 error-compensated (fp32-class accuracy).
//   CAUSAL_OUT: skip n0 > m0+127 tiles. CAUSAL_K: k-loop only to m0+128.
//   NXFAST: n tiles on blockIdx.x (else m tiles fastest, for logits L2 reuse).
// CTA 128x128, BK=16, double-buffered smem, 8 warps as 2(M) x 4(N).
template <int NPASS, bool BNT, bool CAUSAL_OUT, bool CAUSAL_K, bool BIAS, bool NXFAST>
__global__ __launch_bounds__(256)
void mma_gemm(GemmPtrs p, const float* __restrict__ bias,
              int M, int N, int K, float scale) {
    const int n0 = (NXFAST ? blockIdx.x : blockIdx.y) * 128;
    const int m0 = (NXFAST ? blockIdx.y : blockIdx.x) * 128;
    if (CAUSAL_OUT && n0 > m0 + 127) return;

    const float* __restrict__ A = p.A[blockIdx.z];
    const float* __restrict__ B = p.B[blockIdx.z];
    float* __restrict__ C       = p.C[blockIdx.z];

    const int kmax = CAUSAL_K ? ((m0 + 128 < K) ? m0 + 128 : K) : K;

    __shared__ __align__(16) float As[2][128][LPAD];
    constexpr int BROWS = BNT ? 128 : 16;
    constexpr int BCOLS = BNT ? LPAD : 132;
    __shared__ __align__(16) float Bs[2][BROWS][BCOLS];

    const int tid = threadIdx.x;
    const int lane = tid & 31;
    const int wid = tid >> 5;
    const int warpM = wid >> 2;
    const int warpN = wid & 3;
    const int qr = lane >> 2;
    const int qc = lane & 3;

    const int frow0 = tid >> 2;          // rows 0..63
    const int frow1 = (tid + 256) >> 2;  // rows 64..127
    const int fc4 = tid & 3;
    const int kr0 = tid >> 5;            // NN B: k rows 0..7 (l=0), +8 (l=1)
    const int c4n = tid & 31;

    float acc[4][4][4] = {};

    float4 av0, av1, bv0, bv1;

    // ---- prologue: fetch + store k-tile 0 ----
    av0 = *(const float4*)&A[(size_t)(m0 + frow0) * K + fc4 * 4];
    av1 = *(const float4*)&A[(size_t)(m0 + frow1) * K + fc4 * 4];
    if (BNT) {
        bv0 = *(const float4*)&B[(size_t)(n0 + frow0) * K + fc4 * 4];
        bv1 = *(const float4*)&B[(size_t)(n0 + frow1) * K + fc4 * 4];
    } else {
        bv0 = *(const float4*)&B[(size_t)(kr0)     * N + n0 + c4n * 4];
        bv1 = *(const float4*)&B[(size_t)(kr0 + 8) * N + n0 + c4n * 4];
    }
    *(float4*)&As[0][frow0][fc4 * 4] = av0;
    *(float4*)&As[0][frow1][fc4 * 4] = av1;
    if (BNT) {
        *(float4*)&Bs[0][frow0 % BROWS][(fc4 * 4) % BCOLS] = bv0;  // frow<128 ok
        *(float4*)&Bs[0][frow1 % BROWS][(fc4 * 4) % BCOLS] = bv1;
    } else {
        *(float4*)&Bs[0][kr0 % BROWS][(c4n * 4) % BCOLS] = bv0;
        *(float4*)&Bs[0][(kr0 + 8) % BROWS][(c4n * 4) % BCOLS] = bv1;
    }
    __syncthreads();

    const int NIT = kmax / 16;
    for (int it = 0; it < NIT; it++) {
        const int cur = it & 1;
        if (it + 1 < NIT) {
            const int k0 = (it + 1) * 16;
            av0 = *(const float4*)&A[(size_t)(m0 + frow0) * K + k0 + fc4 * 4];
            av1 = *(const float4*)&A[(size_t)(m0 + frow1) * K + k0 + fc4 * 4];
            if (BNT) {
                bv0 = *(const float4*)&B[(size_t)(n0 + frow0) * K + k0 + fc4 * 4];
                bv1 = *(const float4*)&B[(size_t)(n0 + frow1) * K + k0 + fc4 * 4];
            } else {
                bv0 = *(const float4*)&B[(size_t)(k0 + kr0)     * N + n0 + c4n * 4];
                bv1 = *(const float4*)&B[(size_t)(k0 + kr0 + 8) * N + n0 + c4n * 4];
            }
        }

#pragma unroll
        for (int ks = 0; ks < 2; ks++) {
            uint32_t ah[4][4], al[4][4], bh[4][2], bl[4][2];
#pragma unroll
            for (int mt = 0; mt < 4; mt++) {
                const int r = warpM * 64 + mt * 16 + qr;
                float x0 = As[cur][r][ks * 8 + qc];
                float x1 = As[cur][r + 8][ks * 8 + qc];
                float x2 = As[cur][r][ks * 8 + qc + 4];
                float x3 = As[cur][r + 8][ks * 8 + qc + 4];
                ah[mt][0] = f2tf32(x0); ah[mt][1] = f2tf32(x1);
                ah[mt][2] = f2tf32(x2); ah[mt][3] = f2tf32(x3);
                if (NPASS == 3) {
                    al[mt][0] = f2tf32(x0 - __uint_as_float(ah[mt][0]));
                    al[mt][1] = f2tf32(x1 - __uint_as_float(ah[mt][1]));
                    al[mt][2] = f2tf32(x2 - __uint_as_float(ah[mt][2]));
                    al[mt][3] = f2tf32(x3 - __uint_as_float(ah[mt][3]));
                }
            }
#pragma unroll
            for (int nt = 0; nt < 4; nt++) {
                const int n = warpN * 32 + nt * 8 + qr;
                float y0, y1;
                if (BNT) {
                    y0 = Bs[cur][n % BROWS][(ks * 8 + qc) % BCOLS];
                    y1 = Bs[cur][n % BROWS][(ks * 8 + qc + 4) % BCOLS];
                } else {
                    y0 = Bs[cur][(ks * 8 + qc) % BROWS][n % BCOLS];
                    y1 = Bs[cur][(ks * 8 + qc + 4) % BROWS][n % BCOLS];
                }
                bh[nt][0] = f2tf32(y0); bh[nt][1] = f2tf32(y1);
                if (NPASS == 3) {
                    bl[nt][0] = f2tf32(y0 - __uint_as_float(bh[nt][0]));
                    bl[nt][1] = f2tf32(y1 - __uint_as_float(bh[nt][1]));
                }
            }
#pragma unroll
            for (int mt = 0; mt < 4; mt++)
#pragma unroll
                for (int nt = 0; nt < 4; nt++) {
                    mma_tf32(acc[mt][nt], ah[mt], bh[nt]);
                    if (NPASS == 3) {
                        uint32_t abl[4] = {ah[mt][0], ah[mt][1], ah[mt][2], ah[mt][3]};
                        mma_tf32(acc[mt][nt], abl, bl[nt]);
                        mma_tf32(acc[mt][nt], al[mt], bh[nt]);
                    }
                }
        }
        __syncthreads();

        if (it + 1 < NIT) {
            const int nxt = cur ^ 1;
            *(float4*)&As[nxt][frow0][fc4 * 4] = av0;
            *(float4*)&As[nxt][frow1][fc4 * 4] = av1;
            if (BNT) {
                *(float4*)&Bs[nxt][frow0 % BROWS][(fc4 * 4) % BCOLS] = bv0;
                *(float4*)&Bs[nxt][frow1 % BROWS][(fc4 * 4) % BCOLS] = bv1;
            } else {
                *(float4*)&Bs[nxt][kr0 % BROWS][(c4n * 4) % BCOLS] = bv0;
                *(float4*)&Bs[nxt][(kr0 + 8) % BROWS][(c4n * 4) % BCOLS] = bv1;
            }
            __syncthreads();
        }
    }

    // ---- epilogue ----
#pragma unroll
    for (int mt = 0; mt < 4; mt++) {
        const int r = m0 + warpM * 64 + mt * 16 + qr;
#pragma unroll
        for (int nt = 0; nt < 4; nt++) {
            const int c = n0 + warpN * 32 + nt * 8 + qc * 2;
            float2 bb = BIAS ? *(const float2*)&bias[c] : make_float2(0.f, 0.f);
            float2 v0, v1;
            v0.x = acc[mt][nt][0] * scale + bb.x;
            v0.y = acc[mt][nt][1] * scale + bb.y;
            v1.x = acc[mt][nt][2] * scale + bb.x;
            v1.y = acc[mt][nt][3] * scale + bb.y;
            *(float2*)&C[(size_t)r * N + c] = v0;
            *(float2*)&C[(size_t)(r + 8) * N + c] = v1;
        }
    }
}

// ---------------- stage 4: causal row softmax (in place on g_S) -------------
__global__ void softmax_causal_kernel() {
    int row = blockIdx.x;
    int b = row / SEQ;
    int q = row & (SEQ - 1);
    float* r = g_S + (size_t)b * SEQ * SEQ + (size_t)q * SEQ;
    const int len = q + 1;

    __shared__ float redm[8];
    __shared__ float reds[8];
    __shared__ float bc[2];

    float m = -INFINITY;
    for (int i = threadIdx.x; i < len; i += 256) m = fmaxf(m, r[i]);
#pragma unroll
    for (int o = 16; o; o >>= 1) m = fmaxf(m, __shfl_xor_sync(0xffffffffu, m, o));
    if ((threadIdx.x & 31) == 0) redm[threadIdx.x >> 5] = m;
    __syncthreads();
    if (threadIdx.x == 0) {
        float v = redm[0];
#pragma unroll
        for (int w = 1; w < 8; w++) v = fmaxf(v, redm[w]);
        bc[0] = v;
    }
    __syncthreads();
    const float rmax = bc[0];

    float s = 0.f;
    for (int i = threadIdx.x; i < len; i += 256) {
        float e = __expf(r[i] - rmax);
        r[i] = e;
        s += e;
    }
#pragma unroll
    for (int o = 16; o; o >>= 1) s += __shfl_xor_sync(0xffffffffu, s, o);
    if ((threadIdx.x & 31) == 0) reds[threadIdx.x >> 5] = s;
    __syncthreads();
    if (threadIdx.x == 0) {
        float v = reds[0];
#pragma unroll
        for (int w = 1; w < 8; w++) v += reds[w];
        bc[1] = 1.0f / v;
    }
    __syncthreads();
    const float inv = bc[1];

    for (int i = threadIdx.x; i < len; i += 256) r[i] *= inv;
    for (int i = len + threadIdx.x; i < SEQ; i += 256) r[i] = 0.f;
}

// ---------------- launch ----------------------------------------------------
extern "C" void kernel_launch(void* const* d_in, const int* in_sizes, int n_in,
                              void* d_out, int out_size) {
    const int*   x   = (const int*)d_in[0];
    const float* emb = (const float*)d_in[1];
    const float* Wq  = (const float*)d_in[2];
    const float* Wk  = (const float*)d_in[3];
    const float* Wv  = (const float*)d_in[4];
    const float* Wh  = (const float*)d_in[5];
    const float* bh  = (const float*)d_in[6];
    float* out = (float*)d_out;

    float *h, *Q, *K, *V, *S, *C;
    cudaGetSymbolAddress((void**)&h, g_h);
    cudaGetSymbolAddress((void**)&Q, g_Q);
    cudaGetSymbolAddress((void**)&K, g_K);
    cudaGetSymbolAddress((void**)&V, g_V);
    cudaGetSymbolAddress((void**)&S, g_S);
    cudaGetSymbolAddress((void**)&C, g_C);

    const float sscale = 22.627416997969522f;  // sqrt(512)
    const dim3 blk(256);

    // 1) embedding + positional encoding
    embed_pe_kernel<<<NTOK, 128>>>(x, emb);

    // 2) fused Q/K/V projections (3xTF32, z selects weight/output)
    {
        GemmPtrs p;
        p.A[0] = p.A[1] = p.A[2] = h;
        p.B[0] = Wq; p.B[1] = Wk; p.B[2] = Wv;
        p.C[0] = Q;  p.C[1] = K;  p.C[2] = V;
        mma_gemm<3, true, false, false, false, true>
            <<<dim3(KQD / 128, NTOK / 128, 3), blk>>>(p, nullptr, NTOK, KQD, EMBED, 1.f);
    }

    // 3) scores = sqrt(512) * Q K^T (3xTF32, causal output tiles skipped)
    {
        GemmPtrs p;
        for (int b = 0; b < NB; b++) {
            p.A[b] = Q + (size_t)b * SEQ * KQD;
            p.B[b] = K + (size_t)b * SEQ * KQD;
            p.C[b] = S + (size_t)b * SEQ * SEQ;
        }
        p.A[2] = p.B[2] = p.C[2] = nullptr;
        mma_gemm<3, true, true, false, false, true>
            <<<dim3(SEQ / 128, SEQ / 128, NB), blk>>>(p, nullptr, SEQ, SEQ, KQD, sscale);
    }

    // 4) causal softmax in place
    softmax_causal_kernel<<<NTOK, 256>>>();

    // 5) ctx = attn @ V (3xTF32 NN, k-loop trimmed to the causal range)
    {
        GemmPtrs p;
        for (int b = 0; b < NB; b++) {
            p.A[b] = S + (size_t)b * SEQ * SEQ;
            p.B[b] = V + (size_t)b * SEQ * VDIM;
            p.C[b] = C + (size_t)b * SEQ * VDIM;
        }
        p.A[2] = p.B[2] = p.C[2] = nullptr;
        mma_gemm<3, false, false, true, false, true>
            <<<dim3(VDIM / 128, SEQ / 128, NB), blk>>>(p, nullptr, SEQ, VDIM, SEQ, 1.f);
    }

    // 6) logits = ctx @ Wh^T + bh (single-pass tf32; m tiles on fast axis for L2)
    {
        GemmPtrs p;
        p.A[0] = C; p.B[0] = Wh; p.C[0] = out;
        p.A[1] = p.A[2] = p.B[1] = p.B[2] = nullptr;
        p.C[1] = p.C[2] = nullptr;
        mma_gemm<1, true, false, false, true, false>
            <<<dim3(NTOK / 128, VOCAB / 128, 1), blk>>>(p, bh, NTOK, VOCAB, VDIM, 1.f);
    }
}